// round 1
// baseline (speedup 1.0000x reference)
#include <cuda_runtime.h>

#define T_SEQ 2048
#define BATCH 64
#define INPUT 16
#define HEADS 8
#define HID   64
#define GATES 256   // 4*HID

// 2048*64*8*64 floats = 268 MB scratch for the per-step hidden states
__device__ float g_hs[T_SEQ * BATCH * HEADS * HID];

__device__ __forceinline__ float fsigmoid(float x) {
    float e = __expf(-x);
    return __fdividef(1.0f, 1.0f + e);
}
__device__ __forceinline__ float ftanh_fast(float x) {
    float e = __expf(-2.0f * x);
    return __fdividef(2.0f, 1.0f + e) - 1.0f;
}

// One CTA per (batch, head) chain. 256 threads, thread g owns gate row g.
__global__ __launch_bounds__(256, 2)
void lstm_chain_kernel(const float* __restrict__ x,
                       const float* __restrict__ W_ih,
                       const float* __restrict__ W_hh,
                       const float* __restrict__ b_ih,
                       const float* __restrict__ b_hh) {
    const int b = blockIdx.x >> 3;
    const int h = blockIdx.x & 7;
    const int g = threadIdx.x;

    __shared__ __align__(16) float sh_h[HID];
    __shared__ __align__(16) float sh_x[INPUT];
    __shared__ float sh_act[GATES];

    // Weights for this gate row -> registers
    float w[HID];
    {
        const float* wr = W_hh + (h * GATES + g) * HID;
#pragma unroll
        for (int k = 0; k < HID; k++) w[k] = wr[k];
    }
    float xw[INPUT];
    {
        const float* xr = W_ih + (h * GATES + g) * INPUT;
#pragma unroll
        for (int i = 0; i < INPUT; i++) xw[i] = xr[i];
    }
    const float bias = b_ih[h * GATES + g] + b_hh[h * GATES + g];

    float c = 0.0f;
    if (g < HID)   sh_h[g] = 0.0f;
    if (g < INPUT) sh_x[g] = x[b * INPUT + g];   // x[t=0, b, :]
    __syncthreads();

    const int gate_type = g >> 6;  // 0:i 1:f 2:g 3:o (warp-uniform)

#pragma unroll 1
    for (int t = 0; t < T_SEQ; t++) {
        // Prefetch next x into a register (latency hidden under the matvec)
        float xreg = 0.0f;
        if (g < INPUT && t + 1 < T_SEQ)
            xreg = x[((t + 1) * BATCH + b) * INPUT + g];

        // z = bias + W_ih[g,:] . x_t + W_hh[g,:] . h_{t-1}
        float a0 = bias, a1 = 0.0f, a2 = 0.0f, a3 = 0.0f;
        const float4* x4 = (const float4*)sh_x;
#pragma unroll
        for (int q = 0; q < INPUT / 4; q++) {
            float4 xv = x4[q];
            a0 = fmaf(xw[4 * q + 0], xv.x, a0);
            a1 = fmaf(xw[4 * q + 1], xv.y, a1);
            a2 = fmaf(xw[4 * q + 2], xv.z, a2);
            a3 = fmaf(xw[4 * q + 3], xv.w, a3);
        }
        const float4* h4 = (const float4*)sh_h;
#pragma unroll
        for (int q = 0; q < HID / 4; q++) {
            float4 hv = h4[q];
            a0 = fmaf(w[4 * q + 0], hv.x, a0);
            a1 = fmaf(w[4 * q + 1], hv.y, a1);
            a2 = fmaf(w[4 * q + 2], hv.z, a2);
            a3 = fmaf(w[4 * q + 3], hv.w, a3);
        }
        float z = (a0 + a1) + (a2 + a3);

        float a = (gate_type == 2) ? ftanh_fast(z) : fsigmoid(z);
        sh_act[g] = a;
        __syncthreads();   // B1: all reads of sh_h/sh_x done, sh_act visible

        if (g < HID) {
            float iv = sh_act[g];
            float fv = sh_act[HID + g];
            float gv = sh_act[2 * HID + g];
            float ov = sh_act[3 * HID + g];
            c = fmaf(fv, c, iv * gv);
            float hv = ov * ftanh_fast(c);
            sh_h[g] = hv;
            g_hs[((t * BATCH + b) * HEADS + h) * HID + g] = hv;  // coalesced 256B
        }
        if (g < INPUT) sh_x[g] = xreg;
        __syncthreads();   // B2: new sh_h/sh_x visible before next step
    }
}

// Finalize: out[t,b,h] = hs[t,b,h,:].W_lin[h] + b_lin[h];
//           lstm_output[t,b,k] = sum_h hs[t,b,h,k]
// One block of 256 threads handles 4 (t,b) pairs.
__global__ __launch_bounds__(256)
void finalize_kernel(const float* __restrict__ W_lin,
                     const float* __restrict__ b_lin,
                     float* __restrict__ out,
                     float* __restrict__ lstm_out) {
    const int local = threadIdx.x >> 6;   // 0..3
    const int k     = threadIdx.x & 63;
    const int tb    = blockIdx.x * 4 + local;   // < T_SEQ*BATCH

    __shared__ float red[4][HEADS][HID];

    const float* hp = g_hs + (size_t)tb * (HEADS * HID);
    float s = 0.0f;
#pragma unroll
    for (int h = 0; h < HEADS; h++) {
        float v = hp[h * HID + k];
        s += v;
        red[local][h][k] = v * W_lin[h * HID + k];
    }
    lstm_out[(size_t)tb * HID + k] = s;
    __syncthreads();

    if (threadIdx.x < 32) {
        const int l2 = threadIdx.x >> 3;
        const int h  = threadIdx.x & 7;
        const float* r = red[l2][h];
        float acc = 0.0f;
#pragma unroll
        for (int kk = 0; kk < HID; kk++) acc += r[kk];
        out[(size_t)(blockIdx.x * 4 + l2) * HEADS + h] = acc + b_lin[h];
    }
}

extern "C" void kernel_launch(void* const* d_in, const int* in_sizes, int n_in,
                              void* d_out, int out_size) {
    const float* x     = (const float*)d_in[0];  // (T,B,I)
    const float* W_ih  = (const float*)d_in[1];  // (H,4h,I)
    const float* W_hh  = (const float*)d_in[2];  // (H,4h,h)
    const float* b_ih  = (const float*)d_in[3];  // (H,4h)
    const float* b_hh  = (const float*)d_in[4];  // (H,4h)
    const float* W_lin = (const float*)d_in[5];  // (H,h)
    const float* b_lin = (const float*)d_in[6];  // (H,)

    float* out      = (float*)d_out;                          // (T,B,H)
    float* lstm_out = out + (size_t)T_SEQ * BATCH * HEADS;    // (T,B,hid)

    lstm_chain_kernel<<<BATCH * HEADS, 256>>>(x, W_ih, W_hh, b_ih, b_hh);
    finalize_kernel<<<(T_SEQ * BATCH) / 4, 256>>>(W_lin, b_lin, out, lstm_out);
}